// round 1
// baseline (speedup 1.0000x reference)
#include <cuda_runtime.h>
#include <cstdint>

#define VOCAB  16000
#define EMBED  256
#define HIDDEN 512
#define BATCH  8
#define SEQ    2048
#define M_TOK  (BATCH * SEQ)   // 16384

// 32 MB scratch: holds x_proj, then overwritten in-place per timestep with h_t
// (the RNN output sequence), then read as the A matrix of the logits GEMM.
__device__ float g_buf[(size_t)M_TOK * HIDDEN];

// int64-vs-int32 token dtype detection flag
__device__ int g_is64;

// ---------------------------------------------------------------------------
// Kernel 0: detect whether x is int64 (all high words of first 128 elements 0)
// or int32 (odd slots are real token values, ~never all zero).
// ---------------------------------------------------------------------------
__global__ void detect_kernel(const int* __restrict__ x32) {
    int ok = 1;
    for (int i = 0; i < 128; i++)
        if (x32[2 * i + 1] != 0) ok = 0;
    g_is64 = ok;
}

// ---------------------------------------------------------------------------
// Kernel 1: x_proj[m, h] = sum_e embedding[x[m]][e] * W_ih[h][e] + b_ih[h]
// Tiled fp32 GEMM with gathered A rows. M=16384, N=512, K=256.
// Block tile 128x128, 256 threads, 8x8 per thread. Grid (4, 128).
// ---------------------------------------------------------------------------
__global__ __launch_bounds__(256, 2) void xproj_kernel(
    const long long* __restrict__ x64,
    const int*       __restrict__ x32,
    const float*     __restrict__ emb,
    const float*     __restrict__ W_ih,
    const float*     __restrict__ b_ih)
{
    __shared__ float As[8][132];
    __shared__ float Bs[8][132];
    __shared__ int   xid[128];

    const int m0 = blockIdx.y * 128;
    const int n0 = blockIdx.x * 128;
    const int tid = threadIdx.x;

    if (tid < 128) {
        int m = m0 + tid;
        xid[tid] = g_is64 ? (int)x64[m] : x32[m];
    }
    __syncthreads();

    const int tx = tid & 15, ty = tid >> 4;
    const int lrow = tid >> 1;
    const int lq   = (tid & 1) * 4;

    const long  aBase = (long)xid[lrow] * EMBED + lq;
    const float* bRow = W_ih + (long)(n0 + lrow) * EMBED + lq;

    float acc[8][8];
    #pragma unroll
    for (int i = 0; i < 8; i++)
        #pragma unroll
        for (int j = 0; j < 8; j++) acc[i][j] = 0.f;

    for (int k0 = 0; k0 < EMBED; k0 += 8) {
        float4 av = *(const float4*)(emb + aBase + k0);
        float4 bv = *(const float4*)(bRow + k0);
        __syncthreads();
        As[lq + 0][lrow] = av.x; As[lq + 1][lrow] = av.y;
        As[lq + 2][lrow] = av.z; As[lq + 3][lrow] = av.w;
        Bs[lq + 0][lrow] = bv.x; Bs[lq + 1][lrow] = bv.y;
        Bs[lq + 2][lrow] = bv.z; Bs[lq + 3][lrow] = bv.w;
        __syncthreads();
        #pragma unroll
        for (int kk = 0; kk < 8; kk++) {
            float a[8], bb[8];
            #pragma unroll
            for (int i = 0; i < 8; i++) a[i] = As[kk][ty * 8 + i];
            #pragma unroll
            for (int j = 0; j < 8; j++) bb[j] = Bs[kk][tx * 8 + j];
            #pragma unroll
            for (int i = 0; i < 8; i++)
                #pragma unroll
                for (int j = 0; j < 8; j++)
                    acc[i][j] = fmaf(a[i], bb[j], acc[i][j]);
        }
    }

    float bias[8];
    #pragma unroll
    for (int j = 0; j < 8; j++) bias[j] = b_ih[n0 + tx * 8 + j];

    #pragma unroll
    for (int i = 0; i < 8; i++) {
        size_t o = (size_t)(m0 + ty * 8 + i) * HIDDEN + n0 + tx * 8;
        float4 v0 = make_float4(acc[i][0] + bias[0], acc[i][1] + bias[1],
                                acc[i][2] + bias[2], acc[i][3] + bias[3]);
        float4 v1 = make_float4(acc[i][4] + bias[4], acc[i][5] + bias[5],
                                acc[i][6] + bias[6], acc[i][7] + bias[7]);
        *(float4*)(g_buf + o)     = v0;
        *(float4*)(g_buf + o + 4) = v1;
    }
}

// ---------------------------------------------------------------------------
// Kernel 2: the sequential RNN scan.
// One cluster of 8 CTAs per batch (8 clusters). CTA c of batch b owns output
// rows [c*64, c*64+64) of W_hh, held entirely in registers (128 floats/thread).
// h lives replicated in every CTA's SMEM, double-buffered; each step's new
// chunk is pushed to all 8 peers with st.shared::cluster, then one
// cluster barrier per step.
// Thread layout: tid = r*4 + q; r = output row (0..63), q = K-quarter (0..3).
// h SMEM is segment-padded (132 floats per 128-segment) for conflict-free
// float4 broadcast loads.
// ---------------------------------------------------------------------------
__global__ void __launch_bounds__(256, 1) __cluster_dims__(8, 1, 1)
rnn_kernel(const float* __restrict__ hidden,
           const float* __restrict__ W_hh,
           const float* __restrict__ b_hh,
           float* __restrict__ out,
           int hf_off)
{
    __shared__ float hbuf[2][4 * 132];   // 2 x 528 floats

    const int tid = threadIdx.x;
    unsigned c;
    asm("mov.u32 %0, %%cluster_ctarank;" : "=r"(c));
    const int b = blockIdx.y;

    const int q = tid & 3;          // K quarter: cols [q*128, q*128+128)
    const int r = tid >> 2;         // local row 0..63
    const int row = (int)c * 64 + r;

    // W_hh slice into registers: w4[i] = W_hh[row][q*128 + 4i .. +3]
    float4 w4[32];
    const float4* wp = (const float4*)(W_hh + (long)row * HIDDEN + q * 128);
    #pragma unroll
    for (int i = 0; i < 32; i++) w4[i] = wp[i];

    // init h buffer 0 with initial hidden state (padded layout)
    for (int i = tid; i < HIDDEN; i += 256)
        hbuf[0][(i >> 7) * 132 + (i & 127)] = hidden[b * HIDDEN + i];

    const float bhh_r = (q == 0) ? b_hh[row] : 0.f;

    // shared-memory byte address of this row's slot in each buffer
    uint32_t sbase;
    {
        void* p = (void*)hbuf;
        asm("{ .reg .u64 t; cvta.to.shared.u64 t, %1; cvt.u32.u64 %0, t; }"
            : "=r"(sbase) : "l"(p));
    }
    const int pp = (row >> 7) * 132 + (row & 127);
    const uint32_t slot0 = sbase + (uint32_t)pp * 4u;
    const uint32_t slot1 = sbase + (uint32_t)(528 + pp) * 4u;

    const size_t xpi = (size_t)b * SEQ * HIDDEN + row;
    float xv = (q == 0) ? g_buf[xpi] : 0.f;

    __syncthreads();

    #pragma unroll 1
    for (int t = 0; t < SEQ; t++) {
        float xv_next = 0.f;
        if (q == 0 && t + 1 < SEQ)
            xv_next = g_buf[xpi + (size_t)(t + 1) * HIDDEN];

        const float* hs = &hbuf[t & 1][q * 132];
        float acc = 0.f;
        #pragma unroll
        for (int i = 0; i < 32; i++) {
            float4 h4 = *(const float4*)(hs + 4 * i);
            acc = fmaf(w4[i].x, h4.x, acc);
            acc = fmaf(w4[i].y, h4.y, acc);
            acc = fmaf(w4[i].z, h4.z, acc);
            acc = fmaf(w4[i].w, h4.w, acc);
        }
        // reduce over the 4 K-quarters (lanes differing in bits 0,1)
        acc += __shfl_xor_sync(0xffffffffu, acc, 1);
        acc += __shfl_xor_sync(0xffffffffu, acc, 2);

        if (q == 0) {
            float v = tanhf(acc + xv + bhh_r);
            g_buf[xpi + (size_t)t * HIDDEN] = v;   // output_seq (in-place over xp)
            if (t == SEQ - 1)
                out[hf_off + b * HIDDEN + row] = v;
            const uint32_t dstoff = ((t + 1) & 1) ? slot1 : slot0;
            #pragma unroll
            for (int dst = 0; dst < 8; dst++) {
                asm volatile(
                    "{ .reg .b32 ra;\n\t"
                    "  mapa.shared::cluster.u32 ra, %0, %1;\n\t"
                    "  st.shared::cluster.f32 [ra], %2; }"
                    :: "r"(dstoff), "r"(dst), "f"(v) : "memory");
            }
        }
        asm volatile("barrier.cluster.arrive.aligned;" ::: "memory");
        asm volatile("barrier.cluster.wait.aligned;"   ::: "memory");
        xv = xv_next;
    }
}

// ---------------------------------------------------------------------------
// Kernel 3: logits[m, v] = sum_h outs[m, h] * W_out[v, h] + b_out[v]
// M=16384, N=16000, K=512. fp32 tiled GEMM, 128x128 tiles, 8x8 per thread.
// Grid (125, 128).
// ---------------------------------------------------------------------------
__global__ __launch_bounds__(256, 2) void logits_kernel(
    const float* __restrict__ W_out,
    const float* __restrict__ b_out,
    float* __restrict__ out)
{
    __shared__ float As[8][132];
    __shared__ float Bs[8][132];

    const int m0 = blockIdx.y * 128;
    const int n0 = blockIdx.x * 128;
    const int tid = threadIdx.x;
    const int tx = tid & 15, ty = tid >> 4;
    const int lrow = tid >> 1;
    const int lq   = (tid & 1) * 4;

    const float* aP = g_buf + (size_t)(m0 + lrow) * HIDDEN + lq;
    const float* bP = W_out + (size_t)(n0 + lrow) * HIDDEN + lq;

    float acc[8][8];
    #pragma unroll
    for (int i = 0; i < 8; i++)
        #pragma unroll
        for (int j = 0; j < 8; j++) acc[i][j] = 0.f;

    for (int k0 = 0; k0 < HIDDEN; k0 += 8) {
        float4 av = *(const float4*)(aP + k0);
        float4 bv = *(const float4*)(bP + k0);
        __syncthreads();
        As[lq + 0][lrow] = av.x; As[lq + 1][lrow] = av.y;
        As[lq + 2][lrow] = av.z; As[lq + 3][lrow] = av.w;
        Bs[lq + 0][lrow] = bv.x; Bs[lq + 1][lrow] = bv.y;
        Bs[lq + 2][lrow] = bv.z; Bs[lq + 3][lrow] = bv.w;
        __syncthreads();
        #pragma unroll
        for (int kk = 0; kk < 8; kk++) {
            float a[8], bb[8];
            #pragma unroll
            for (int i = 0; i < 8; i++) a[i] = As[kk][ty * 8 + i];
            #pragma unroll
            for (int j = 0; j < 8; j++) bb[j] = Bs[kk][tx * 8 + j];
            #pragma unroll
            for (int i = 0; i < 8; i++)
                #pragma unroll
                for (int j = 0; j < 8; j++)
                    acc[i][j] = fmaf(a[i], bb[j], acc[i][j]);
        }
    }

    float bias[8];
    #pragma unroll
    for (int j = 0; j < 8; j++) bias[j] = b_out[n0 + tx * 8 + j];

    #pragma unroll
    for (int i = 0; i < 8; i++) {
        size_t o = (size_t)(m0 + ty * 8 + i) * VOCAB + n0 + tx * 8;
        float4 v0 = make_float4(acc[i][0] + bias[0], acc[i][1] + bias[1],
                                acc[i][2] + bias[2], acc[i][3] + bias[3]);
        float4 v1 = make_float4(acc[i][4] + bias[4], acc[i][5] + bias[5],
                                acc[i][6] + bias[6], acc[i][7] + bias[7]);
        *(float4*)(out + o)     = v0;
        *(float4*)(out + o + 4) = v1;
    }
}

// ---------------------------------------------------------------------------
// Inputs (metadata order):
//  0: x        [8, 2048]   int64 (or int32 if JAX x64 disabled — auto-detected)
//  1: hidden   [8, 512]    f32
//  2: embedding[16000,256] f32
//  3: W_ih     [512, 256]  f32
//  4: W_hh     [512, 512]  f32
//  5: b_ih     [512]       f32
//  6: b_hh     [512]       f32
//  7: W_out    [16000,512] f32
//  8: b_out    [16000]     f32
// Output: logits [8,2048,16000] f32, then h_final [8,512] f32.
// ---------------------------------------------------------------------------
extern "C" void kernel_launch(void* const* d_in, const int* in_sizes, int n_in,
                              void* d_out, int out_size)
{
    const long long* x64   = (const long long*)d_in[0];
    const int*       x32   = (const int*)d_in[0];
    const float* hidden    = (const float*)d_in[1];
    const float* embedding = (const float*)d_in[2];
    const float* W_ih      = (const float*)d_in[3];
    const float* W_hh      = (const float*)d_in[4];
    const float* b_ih      = (const float*)d_in[5];
    const float* b_hh      = (const float*)d_in[6];
    const float* W_out     = (const float*)d_in[7];
    const float* b_out     = (const float*)d_in[8];
    float* out = (float*)d_out;

    const int hf_off = out_size - BATCH * HIDDEN;   // h_final tail offset

    detect_kernel<<<1, 1>>>(x32);

    xproj_kernel<<<dim3(4, 128), 256>>>(x64, x32, embedding, W_ih, b_ih);

    rnn_kernel<<<dim3(8, 8), 256>>>(hidden, W_hh, b_hh, out, hf_off);

    logits_kernel<<<dim3(125, 128), 256>>>(W_out, b_out, out);
}

// round 3
// speedup vs baseline: 2.0036x; 2.0036x over previous
#include <cuda_runtime.h>
#include <cstdint>

#define VOCAB  16000
#define EMBED  256
#define HIDDEN 512
#define BATCH  8
#define SEQ    2048
#define M_TOK  (BATCH * SEQ)   // 16384

// Scratch: x_proj then RNN output sequence (tf32-rounded) = A of logits GEMM.
__device__ float g_buf[(size_t)M_TOK * HIDDEN];
// W_out pre-rounded to tf32 (unbiased RN before HW tf32 MMA).
__device__ float g_wt[(size_t)VOCAB * HIDDEN];
// token dtype flag
__device__ int g_is64;

__device__ __forceinline__ uint32_t f2tf32(float f) {
    uint32_t r;
    asm("cvt.rn.tf32.f32 %0, %1;" : "=r"(r) : "f"(f));
    return r;
}

#define CP_A16(dst, src) \
    asm volatile("cp.async.cg.shared.global [%0], [%1], 16;" :: "r"(dst), "l"(src) : "memory")
#define CP_A16Z(dst, src, sz) \
    asm volatile("cp.async.cg.shared.global [%0], [%1], 16, %2;" :: "r"(dst), "l"(src), "r"(sz) : "memory")
#define CP_COMMIT() asm volatile("cp.async.commit_group;" ::: "memory")
#define CP_WAIT(n)  asm volatile("cp.async.wait_group %0;" :: "n"(n) : "memory")

// ---------------------------------------------------------------------------
// Kernel 0: int64-vs-int32 token detection
// ---------------------------------------------------------------------------
__global__ void detect_kernel(const int* __restrict__ x32) {
    int ok = 1;
    for (int i = 0; i < 128; i++)
        if (x32[2 * i + 1] != 0) ok = 0;
    g_is64 = ok;
}

// ---------------------------------------------------------------------------
// Kernel 0b: round W_out to tf32 (RN) into g_wt.
// ---------------------------------------------------------------------------
__global__ __launch_bounds__(256) void wconv_kernel(const float* __restrict__ w) {
    int t = blockIdx.x * 256 + threadIdx.x;       // 0..511999
    const float4* src = (const float4*)w;
    float4* dst = (float4*)g_wt;
    #pragma unroll
    for (int i = 0; i < 4; i++) {
        int idx = t + i * 512000;
        float4 v = src[idx];
        float4 o;
        o.x = __uint_as_float(f2tf32(v.x));
        o.y = __uint_as_float(f2tf32(v.y));
        o.z = __uint_as_float(f2tf32(v.z));
        o.w = __uint_as_float(f2tf32(v.w));
        dst[idx] = o;
    }
}

// ---------------------------------------------------------------------------
// Kernel 1: x_proj = gather(embedding, x) @ W_ih^T + b_ih  (fp32 SIMT, exact)
// ---------------------------------------------------------------------------
__global__ __launch_bounds__(256, 2) void xproj_kernel(
    const long long* __restrict__ x64,
    const int*       __restrict__ x32,
    const float*     __restrict__ emb,
    const float*     __restrict__ W_ih,
    const float*     __restrict__ b_ih)
{
    __shared__ float As[8][132];
    __shared__ float Bs[8][132];
    __shared__ int   xid[128];

    const int m0 = blockIdx.y * 128;
    const int n0 = blockIdx.x * 128;
    const int tid = threadIdx.x;

    if (tid < 128) {
        int m = m0 + tid;
        xid[tid] = g_is64 ? (int)x64[m] : x32[m];
    }
    __syncthreads();

    const int tx = tid & 15, ty = tid >> 4;
    const int lrow = tid >> 1;
    const int lq   = (tid & 1) * 4;

    const long  aBase = (long)xid[lrow] * EMBED + lq;
    const float* bRow = W_ih + (long)(n0 + lrow) * EMBED + lq;

    float acc[8][8];
    #pragma unroll
    for (int i = 0; i < 8; i++)
        #pragma unroll
        for (int j = 0; j < 8; j++) acc[i][j] = 0.f;

    for (int k0 = 0; k0 < EMBED; k0 += 8) {
        float4 av = *(const float4*)(emb + aBase + k0);
        float4 bv = *(const float4*)(bRow + k0);
        __syncthreads();
        As[lq + 0][lrow] = av.x; As[lq + 1][lrow] = av.y;
        As[lq + 2][lrow] = av.z; As[lq + 3][lrow] = av.w;
        Bs[lq + 0][lrow] = bv.x; Bs[lq + 1][lrow] = bv.y;
        Bs[lq + 2][lrow] = bv.z; Bs[lq + 3][lrow] = bv.w;
        __syncthreads();
        #pragma unroll
        for (int kk = 0; kk < 8; kk++) {
            float a[8], bb[8];
            #pragma unroll
            for (int i = 0; i < 8; i++) a[i] = As[kk][ty * 8 + i];
            #pragma unroll
            for (int j = 0; j < 8; j++) bb[j] = Bs[kk][tx * 8 + j];
            #pragma unroll
            for (int i = 0; i < 8; i++)
                #pragma unroll
                for (int j = 0; j < 8; j++)
                    acc[i][j] = fmaf(a[i], bb[j], acc[i][j]);
        }
    }

    float bias[8];
    #pragma unroll
    for (int j = 0; j < 8; j++) bias[j] = b_ih[n0 + tx * 8 + j];

    #pragma unroll
    for (int i = 0; i < 8; i++) {
        size_t o = (size_t)(m0 + ty * 8 + i) * HIDDEN + n0 + tx * 8;
        float4 v0 = make_float4(acc[i][0] + bias[0], acc[i][1] + bias[1],
                                acc[i][2] + bias[2], acc[i][3] + bias[3]);
        float4 v1 = make_float4(acc[i][4] + bias[4], acc[i][5] + bias[5],
                                acc[i][6] + bias[6], acc[i][7] + bias[7]);
        *(float4*)(g_buf + o)     = v0;
        *(float4*)(g_buf + o + 4) = v1;
    }
}

// ---------------------------------------------------------------------------
// Kernel 2: sequential RNN scan (unchanged; fp32-exact recurrence; stores
// tf32-RN-rounded outputs for the tensor-core logits GEMM).
// ---------------------------------------------------------------------------
__global__ void __launch_bounds__(256, 1) __cluster_dims__(8, 1, 1)
rnn_kernel(const float* __restrict__ hidden,
           const float* __restrict__ W_hh,
           const float* __restrict__ b_hh,
           float* __restrict__ out,
           int hf_off)
{
    __shared__ float hbuf[2][4 * 132];

    const int tid = threadIdx.x;
    unsigned c;
    asm("mov.u32 %0, %%cluster_ctarank;" : "=r"(c));
    const int b = blockIdx.y;

    const int q = tid & 3;
    const int r = tid >> 2;
    const int row = (int)c * 64 + r;

    float4 w4[32];
    const float4* wp = (const float4*)(W_hh + (long)row * HIDDEN + q * 128);
    #pragma unroll
    for (int i = 0; i < 32; i++) w4[i] = wp[i];

    for (int i = tid; i < HIDDEN; i += 256)
        hbuf[0][(i >> 7) * 132 + (i & 127)] = hidden[b * HIDDEN + i];

    const float bhh_r = (q == 0) ? b_hh[row] : 0.f;

    uint32_t sbase;
    {
        void* p = (void*)hbuf;
        asm("{ .reg .u64 t; cvta.to.shared.u64 t, %1; cvt.u32.u64 %0, t; }"
            : "=r"(sbase) : "l"(p));
    }
    const int pp = (row >> 7) * 132 + (row & 127);
    const uint32_t slot0 = sbase + (uint32_t)pp * 4u;
    const uint32_t slot1 = sbase + (uint32_t)(528 + pp) * 4u;

    const size_t xpi = (size_t)b * SEQ * HIDDEN + row;
    float xv = (q == 0) ? g_buf[xpi] : 0.f;

    __syncthreads();

    #pragma unroll 1
    for (int t = 0; t < SEQ; t++) {
        float xv_next = 0.f;
        if (q == 0 && t + 1 < SEQ)
            xv_next = g_buf[xpi + (size_t)(t + 1) * HIDDEN];

        const float* hs = &hbuf[t & 1][q * 132];
        float acc = 0.f;
        #pragma unroll
        for (int i = 0; i < 32; i++) {
            float4 h4 = *(const float4*)(hs + 4 * i);
            acc = fmaf(w4[i].x, h4.x, acc);
            acc = fmaf(w4[i].y, h4.y, acc);
            acc = fmaf(w4[i].z, h4.z, acc);
            acc = fmaf(w4[i].w, h4.w, acc);
        }
        acc += __shfl_xor_sync(0xffffffffu, acc, 1);
        acc += __shfl_xor_sync(0xffffffffu, acc, 2);

        if (q == 0) {
            float v = tanhf(acc + xv + bhh_r);
            g_buf[xpi + (size_t)t * HIDDEN] = __uint_as_float(f2tf32(v));
            if (t == SEQ - 1)
                out[hf_off + b * HIDDEN + row] = v;   // exact fp32 h_final
            const uint32_t dstoff = ((t + 1) & 1) ? slot1 : slot0;
            #pragma unroll
            for (int dst = 0; dst < 8; dst++) {
                asm volatile(
                    "{ .reg .b32 ra;\n\t"
                    "  mapa.shared::cluster.u32 ra, %0, %1;\n\t"
                    "  st.shared::cluster.f32 [ra], %2; }"
                    :: "r"(dstoff), "r"(dst), "f"(v) : "memory");
            }
        }
        asm volatile("barrier.cluster.arrive.aligned;" ::: "memory");
        asm volatile("barrier.cluster.wait.aligned;"   ::: "memory");
        xv = xv_next;
    }
}

// ---------------------------------------------------------------------------
// Kernel 3: logits GEMM via warp-level mma.sync tf32 (m16n8k8).
// C[16384,16000] = A[16384,512] @ B^T + bias; A=g_buf, B=g_wt (K-major).
// Block tile 128x256, 8 warps (2x4), warp tile 64x64. K-stage 32,
// 3-stage cp.async pipeline. SMEM row stride 36 floats -> conflict-free
// fragment loads (bank = lane) and 16B-aligned cp.async rows.
// Grid (63, 128), 256 threads, dyn smem 165888 B.
// ---------------------------------------------------------------------------
#define LGA_STRIDE 36                         // floats per SMEM row
#define LGA_BYTES  (128 * LGA_STRIDE * 4)     // 18432
#define LGB_BYTES  (256 * LGA_STRIDE * 4)     // 36864
#define LG_STAGE   (LGA_BYTES + LGB_BYTES)    // 55296
#define LG_SMEM    (3 * LG_STAGE)             // 165888

__global__ __launch_bounds__(256) void logits_mma_kernel(
    const float* __restrict__ b_out,
    float* __restrict__ out)
{
    extern __shared__ float smem[];
    const uint32_t sb = (uint32_t)__cvta_generic_to_shared(smem);

    const int tid  = threadIdx.x;
    const int wid  = tid >> 5;
    const int lane = tid & 31;
    const int gr   = lane >> 2;     // 0..7
    const int gc   = lane & 3;      // 0..3
    const int wm   = wid & 1;       // warp m index (0..1)
    const int wn   = wid >> 1;      // warp n index (0..3)

    const int n0 = blockIdx.x * 256;
    const int m0 = blockIdx.y * 128;

    // per-thread cp.async assignments
    uint32_t aDst[4]; const char* aSrc[4];
    #pragma unroll
    for (int i = 0; i < 4; i++) {
        int ch = tid + i * 256;               // 0..1023
        int row = ch >> 3, q = ch & 7;        // row 0..127, 16B-chunk 0..7
        aDst[i] = (uint32_t)(row * (LGA_STRIDE * 4) + q * 16);
        aSrc[i] = (const char*)(g_buf + (size_t)(m0 + row) * HIDDEN + q * 4);
    }
    uint32_t bDst[8]; const char* bSrc[8]; uint32_t bSz[8];
    #pragma unroll
    for (int i = 0; i < 8; i++) {
        int ch = tid + i * 256;               // 0..2047
        int row = ch >> 3, q = ch & 7;        // row 0..255
        bDst[i] = (uint32_t)(LGA_BYTES + row * (LGA_STRIDE * 4) + q * 16);
        int n = n0 + row;
        bSz[i] = (n < VOCAB) ? 16u : 0u;
        if (n >= VOCAB) n = VOCAB - 1;
        bSrc[i] = (const char*)(g_wt + (size_t)n * HIDDEN + q * 4);
    }

    float c[4][8][4];
    #pragma unroll
    for (int mi = 0; mi < 4; mi++)
        #pragma unroll
        for (int ni = 0; ni < 8; ni++)
            #pragma unroll
            for (int j = 0; j < 4; j++) c[mi][ni][j] = 0.f;

    // prologue: stages 0 and 1
    #pragma unroll
    for (int st = 0; st < 2; st++) {
        uint32_t base = sb + st * LG_STAGE;
        #pragma unroll
        for (int i = 0; i < 4; i++) CP_A16(base + aDst[i], aSrc[i] + st * 128);
        #pragma unroll
        for (int i = 0; i < 8; i++) CP_A16Z(base + bDst[i], bSrc[i] + st * 128, bSz[i]);
        CP_COMMIT();
    }

    // base SMEM float offsets for this warp's fragments
    const int aOffBase = (wm * 64 + gr) * LGA_STRIDE + gc;           // + mi*16*36 (+8*36) (+kk)
    const int bOffBase = 128 * LGA_STRIDE + (wn * 64 + gr) * LGA_STRIDE + gc; // + ni*8*36 (+kk)

    #pragma unroll 1
    for (int ks = 0; ks < 16; ks++) {
        if (ks < 15) CP_WAIT(1); else CP_WAIT(0);
        __syncthreads();

        // issue loads for stage ks+2 into the buffer freed by stage ks-1
        if (ks + 2 < 16) {
            const int st = ks + 2;
            uint32_t base = sb + (uint32_t)(st % 3) * LG_STAGE;
            #pragma unroll
            for (int i = 0; i < 4; i++) CP_A16(base + aDst[i], aSrc[i] + st * 128);
            #pragma unroll
            for (int i = 0; i < 8; i++) CP_A16Z(base + bDst[i], bSrc[i] + st * 128, bSz[i]);
            CP_COMMIT();
        }

        const float* buf = smem + (ks % 3) * (LG_STAGE / 4);
        #pragma unroll
        for (int kk = 0; kk < 32; kk += 8) {
            uint32_t a[4][4];
            #pragma unroll
            for (int mi = 0; mi < 4; mi++) {
                const float* p = buf + aOffBase + mi * 16 * LGA_STRIDE + kk;
                a[mi][0] = __float_as_uint(p[0]);
                a[mi][1] = __float_as_uint(p[8 * LGA_STRIDE]);
                a[mi][2] = __float_as_uint(p[4]);
                a[mi][3] = __float_as_uint(p[8 * LGA_STRIDE + 4]);
            }
            uint32_t b[8][2];
            #pragma unroll
            for (int ni = 0; ni < 8; ni++) {
                const float* p = buf + bOffBase + ni * 8 * LGA_STRIDE + kk;
                b[ni][0] = __float_as_uint(p[0]);
                b[ni][1] = __float_as_uint(p[4]);
            }
            #pragma unroll
            for (int mi = 0; mi < 4; mi++)
                #pragma unroll
                for (int ni = 0; ni < 8; ni++) {
                    asm volatile(
                        "mma.sync.aligned.m16n8k8.row.col.f32.tf32.tf32.f32 "
                        "{%0,%1,%2,%3}, {%4,%5,%6,%7}, {%8,%9}, {%0,%1,%2,%3};"
                        : "+f"(c[mi][ni][0]), "+f"(c[mi][ni][1]),
                          "+f"(c[mi][ni][2]), "+f"(c[mi][ni][3])
                        : "r"(a[mi][0]), "r"(a[mi][1]), "r"(a[mi][2]), "r"(a[mi][3]),
                          "r"(b[ni][0]), "r"(b[ni][1]));
                }
        }
    }

    // epilogue: direct gmem stores + bias
    const int mBase = m0 + wm * 64 + gr;
    const int nBase = n0 + wn * 64 + gc * 2;
    #pragma unroll
    for (int ni = 0; ni < 8; ni++) {
        int col = nBase + ni * 8;
        if (col < VOCAB) {
            float2 bias = *(const float2*)(b_out + col);
            #pragma unroll
            for (int mi = 0; mi < 4; mi++) {
                int r0 = mBase + mi * 16;
                float2 v0 = make_float2(c[mi][ni][0] + bias.x, c[mi][ni][1] + bias.y);
                float2 v1 = make_float2(c[mi][ni][2] + bias.x, c[mi][ni][3] + bias.y);
                *(float2*)(out + (size_t)r0 * VOCAB + col)       = v0;
                *(float2*)(out + (size_t)(r0 + 8) * VOCAB + col) = v1;
            }
        }
    }
}

// ---------------------------------------------------------------------------
// Inputs (metadata order):
//  0:x [8,2048] i64/i32  1:hidden [8,512]  2:embedding [16000,256]
//  3:W_ih [512,256]  4:W_hh [512,512]  5:b_ih [512]  6:b_hh [512]
//  7:W_out [16000,512]  8:b_out [16000]
// Output: logits [8,2048,16000] f32 then h_final [8,512] f32.
// ---------------------------------------------------------------------------
extern "C" void kernel_launch(void* const* d_in, const int* in_sizes, int n_in,
                              void* d_out, int out_size)
{
    const long long* x64   = (const long long*)d_in[0];
    const int*       x32   = (const int*)d_in[0];
    const float* hidden    = (const float*)d_in[1];
    const float* embedding = (const float*)d_in[2];
    const float* W_ih      = (const float*)d_in[3];
    const float* W_hh      = (const float*)d_in[4];
    const float* b_ih      = (const float*)d_in[5];
    const float* b_hh      = (const float*)d_in[6];
    const float* W_out     = (const float*)d_in[7];
    const float* b_out     = (const float*)d_in[8];
    float* out = (float*)d_out;

    const int hf_off = out_size - BATCH * HIDDEN;

    static bool attr_set = false;
    if (!attr_set) {
        cudaFuncSetAttribute(logits_mma_kernel,
                             cudaFuncAttributeMaxDynamicSharedMemorySize, LG_SMEM);
        attr_set = true;
    }

    detect_kernel<<<1, 1>>>(x32);
    wconv_kernel<<<2000, 256>>>(W_out);
    xproj_kernel<<<dim3(4, 128), 256>>>(x64, x32, embedding, W_ih, b_ih);
    rnn_kernel<<<dim3(8, 8), 256>>>(hidden, W_hh, b_hh, out, hf_off);
    logits_mma_kernel<<<dim3(63, 128), 256, LG_SMEM>>>(b_out, out);
}